// round 1
// baseline (speedup 1.0000x reference)
#include <cuda_runtime.h>
#include <math.h>

#define NBATCH 128
#define NSAMP  32768
#define MHALF  16384
#define NFRAME 128
#define NHARM  8
#define PK_STRIDE 416

// ---------------- scratch (device globals; no allocation allowed) ----------------
__device__ float  g_r[NBATCH * NHARM];                 // reduced radians per (b,h)
__device__ float  g_res[NBATCH * NHARM * NFRAME];      // envelope scan results
__device__ float  g_noise[NBATCH * NSAMP];             // filtered+gated noise (16MB)
__device__ float2 g_tw[MHALF];                         // e^{-2*pi*i*k/32768}, k=0..16383

// ---------------- twiddle table (fp64-accurate) ----------------
__global__ void k_tw() {
    int k = blockIdx.x * blockDim.x + threadIdx.x;
    if (k < MHALF) {
        double ang = -6.283185307179586476925286766559 * (double)k / 32768.0;
        g_tw[k] = make_float2((float)cos(ang), (float)sin(ang));
    }
}

// ---------------- prep: softmax-dot f0, radians, envelope scan ----------------
__global__ void k_prep(const float* __restrict__ packed, const float* __restrict__ freqs) {
    int b = blockIdx.x;
    int t = threadIdx.x;           // 128 threads
    const float* p = packed + b * PK_STRIDE;

    __shared__ float  red[128];
    __shared__ double redd[128];
    __shared__ float  s_f0;
    __shared__ float  s_ampf[128];

    float x = p[t];
    red[t] = x;
    __syncthreads();
    for (int s = 64; s > 0; s >>= 1) {
        if (t < s) red[t] = fmaxf(red[t], red[t + s]);
        __syncthreads();
    }
    float mx = red[0];
    __syncthreads();

    float e = expf(x - mx);
    redd[t] = (double)e;
    __syncthreads();
    for (int s = 64; s > 0; s >>= 1) {
        if (t < s) redd[t] += redd[t + s];
        __syncthreads();
    }
    double esum = redd[0];
    __syncthreads();

    redd[t] = (double)e * (double)freqs[t];
    __syncthreads();
    for (int s = 64; s > 0; s >>= 1) {
        if (t < s) redd[t] += redd[t + s];
        __syncthreads();
    }
    if (t == 0) s_f0 = (float)(redd[0] / esum);
    s_ampf[t] = p[256 + t] * 2.0f - 1.0f;   // SL_AMP
    __syncthreads();

    if (t < NHARM) {
        const float NYQ    = 11025.0f;
        const float PIF    = 3.14159265358979323846f;
        const float MINF0  = (float)(40.0 / 11025.0);
        const float F0SPAN = (float)(3000.0 / 11025.0 - 40.0 / 11025.0);
        float f0s = s_f0;
        float f0  = f0s * f0s;
        f0 = f0 * NYQ;
        f0 = MINF0 + f0 * F0SPAN;
        float osc = f0 * (float)(t + 1);
        float rad = osc / NYQ * PIF;
        if (rad >= PIF) rad = 0.0f;
        g_r[b * NHARM + t] = rad;

        float ha = p[384 + t];                 // SL_HAMP
        float hd = 0.5f + p[392 + t] * 0.5f;   // SL_HDEC -> MIN_RES + x*RES_SPAN
        float cur = 0.0f;
        float* dst = g_res + (b * NHARM + t) * NFRAME;
        for (int f = 0; f < NFRAME; f++) {
            cur = fmaxf(cur + s_ampf[f] * ha, 0.0f);
            dst[f] = cur;
            cur *= hd;
        }
    }
}

// ---------------- FFT filter kernel ----------------
__device__ __forceinline__ float interp_amp_gate(const float* s_amp, int n) {
    float c = ((float)n + 0.5f) * (1.0f / 256.0f) - 0.5f;
    c = fminf(fmaxf(c, 0.0f), 127.0f);
    int   i0 = (int)c;
    float w  = c - (float)i0;
    int   i1 = min(i0 + 1, 127);
    float a  = s_amp[i0] * (1.0f - w) + s_amp[i1] * w;
    return a >= 0.0f ? a : 0.2f * a;
}

__device__ __forceinline__ float nf_eval(const float* env, int j) {
    if (j >= MHALF) return 0.0f;      // pad: nf[16384] = 0
    float c = ((float)j + 0.5f) * (16.0f / 16384.0f) - 0.5f;
    c = fminf(fmaxf(c, 0.0f), 15.0f);
    int   i0 = (int)c;
    float w  = c - (float)i0;
    int   i1 = min(i0 + 1, 15);
    return env[i0] * (1.0f - w) + env[i1] * w;
}

__global__ void __launch_bounds__(512, 1)
k_fft(const float* __restrict__ packed, const float* __restrict__ noise,
      const float* __restrict__ gamp) {
    extern __shared__ float2 sd[];    // 16384 complex = 128KB
    __shared__ float s_amp[128];
    __shared__ float s_env[16];

    int b = blockIdx.x;
    int t = threadIdx.x;
    const float* p = packed + b * PK_STRIDE;
    if (t < 128)            s_amp[t]       = p[256 + t] * 2.0f - 1.0f;
    else if (t < 144)       s_env[t - 128] = p[400 + (t - 128)];

    float ga = gamp[0];
    const float2* nz = reinterpret_cast<const float2*>(noise + (size_t)b * NSAMP);

    // load z[n] = 5000*(x[2n] + i x[2n+1]) at bit-reversed positions
    for (int i = t; i < MHALF; i += 512) {
        float2 v = nz[i];
        v.x *= ga; v.y *= ga;
        sd[__brev((unsigned)i) >> 18] = v;
    }
    __syncthreads();

    // forward radix-2 DIT (e^{-}), output natural order
    {
        int shift = 0;
        for (int m = 2; m <= MHALF; m <<= 1, shift++) {
            int half  = m >> 1;
            int tstep = 32768 / m;
            for (int j = t; j < 8192; j += 512) {
                int pos = j & (half - 1);
                int i1  = ((j >> shift) << (shift + 1)) + pos;
                int i2  = i1 + half;
                float2 w = g_tw[pos * tstep];
                float2 u = sd[i1], v = sd[i2];
                float2 tt = make_float2(w.x * v.x - w.y * v.y, w.x * v.y + w.y * v.x);
                sd[i1] = make_float2(u.x + tt.x, u.y + tt.y);
                sd[i2] = make_float2(u.x - tt.x, u.y - tt.y);
            }
            __syncthreads();
        }
    }

    // unpack real spectrum, multiply by nf, repack for inverse (in-place, pair (k, M-k))
    for (int k = t; k <= 8192; k += 512) {
        int kk = (MHALF - k) & (MHALF - 1);
        float2 Zk = sd[k], Zm = sd[kk];
        float2 Xe = make_float2(0.5f * (Zk.x + Zm.x), 0.5f * (Zk.y - Zm.y));
        float2 Xo = make_float2(0.5f * (Zk.y + Zm.y), 0.5f * (Zm.x - Zk.x));
        float a  = nf_eval(s_env, k);
        float bb = nf_eval(s_env, MHALF - k);
        float s = 0.5f * (a + bb), d = 0.5f * (a - bb);
        float2 w  = g_tw[k];  // e^{-2 pi i k / 32768}
        float2 u  = make_float2(w.x * Xo.x - w.y * Xo.y, w.x * Xo.y + w.y * Xo.x);  // w*Xo
        float2 cw = make_float2(w.x * Xe.x + w.y * Xe.y, w.x * Xe.y - w.y * Xe.x);  // conj(w)*Xe
        float2 Ye = make_float2(s * Xe.x + d * u.x,  s * Xe.y + d * u.y);
        float2 Yo = make_float2(d * cw.x + s * Xo.x, d * cw.y + s * Xo.y);
        sd[k]  = make_float2(Ye.x - Yo.y, Ye.y + Yo.x);
        sd[kk] = make_float2(Ye.x + Yo.y, Yo.x - Ye.y);
    }
    __syncthreads();

    // inverse radix-2 DIF (e^{+}), natural in -> bit-reversed out
    {
        int shift = 13;
        for (int m = MHALF; m >= 2; m >>= 1, shift--) {
            int half  = m >> 1;
            int tstep = 32768 / m;
            for (int j = t; j < 8192; j += 512) {
                int pos = j & (half - 1);
                int i1  = ((j >> shift) << (shift + 1)) + pos;
                int i2  = i1 + half;
                float2 u = sd[i1], v = sd[i2];
                float2 dd = make_float2(u.x - v.x, u.y - v.y);
                float2 w  = g_tw[pos * tstep];
                sd[i1] = make_float2(u.x + v.x, u.y + v.y);
                sd[i2] = make_float2(w.x * dd.x + w.y * dd.y, w.x * dd.y - w.y * dd.x); // conj(w)*dd
            }
            __syncthreads();
        }
    }

    // writeout: y[2n]=Re w[n], y[2n+1]=Im w[n]; scale 1/M; gate by amp envelope
    const float sc = 1.0f / 16384.0f;
    float2* gn = reinterpret_cast<float2*>(g_noise + (size_t)b * NSAMP);
    for (int n = t; n < MHALF; n += 512) {
        float2 wv = sd[__brev((unsigned)n) >> 18];
        float a0 = interp_amp_gate(s_amp, 2 * n);
        float a1 = interp_amp_gate(s_amp, 2 * n + 1);
        gn[n] = make_float2(wv.x * sc * a0, wv.y * sc * a1);
    }
}

// ---------------- synth + reduce ----------------
__device__ __forceinline__ float phase_red(float nf, float r) {
    // exact (n+1)*r mod 2pi via FMA residual; result in ~[-pi, pi]
    float pv  = r * nf;
    float err = fmaf(r, nf, -pv);                       // exact product residual
    float k   = rintf(pv * 0.15915494309189535f);      // 1/(2pi)
    float ph  = fmaf(k, -6.2831854820251465f, pv);      // 2pi hi (single-rounded FMA)
    ph = fmaf(k, 1.7484556e-7f, ph);                    // -(2pi lo)
    return ph + err;
}

__global__ void __launch_bounds__(256)
k_synth(const float* __restrict__ oamp, float* __restrict__ out) {
    int g = blockIdx.y;      // 16 groups of 8 batches
    int chunk = blockIdx.x;  // 16 chunks of 2048 samples
    int t = threadIdx.x;

    __shared__ float s_res[64 * 128];  // 8 batches x 8 harmonics x 128 frames
    __shared__ float s_r[64];

    for (int i = t; i < 64 * 128; i += 256)
        s_res[i] = g_res[g * 64 * NFRAME + i];
    if (t < 64) s_r[t] = g_r[g * 64 + t];
    __syncthreads();

    float oa = oamp[0];
    int nbase = chunk * 2048 + t;

    float acc[8];
#pragma unroll
    for (int i = 0; i < 8; i++) acc[i] = 0.0f;

    // noise part: sum of gated noise over the 8 batches of this group
#pragma unroll
    for (int j = 0; j < 8; j++) {
        const float* nb = g_noise + (size_t)(g * 8 + j) * NSAMP;
#pragma unroll
        for (int i = 0; i < 8; i++) acc[i] += nb[nbase + i * 256];
    }

    // oscillator part
#pragma unroll 1
    for (int i = 0; i < 8; i++) {
        int n = nbase + i * 256;
        float c = ((float)n + 0.5f) * (1.0f / 256.0f) - 0.5f;
        c = fminf(fmaxf(c, 0.0f), 127.0f);
        int   i0 = (int)c;
        float w  = c - (float)i0;
        int   i1 = min(i0 + 1, 127);
        float nf = (float)(n + 1);
        float a  = 0.0f;
#pragma unroll 4
        for (int bh = 0; bh < 64; bh++) {
            const float* rr = s_res + bh * 128;
            float rv = rr[i0] * (1.0f - w) + rr[i1] * w;
            float ph = phase_red(nf, s_r[bh]);
            a += rv * sinf(ph);
        }
        acc[i] += a * oa;
    }

#pragma unroll
    for (int i = 0; i < 8; i++)
        out[(size_t)g * NSAMP + nbase + i * 256] = acc[i];
}

// ---------------- launch ----------------
extern "C" void kernel_launch(void* const* d_in, const int* in_sizes, int n_in,
                              void* d_out, int out_size) {
    const float* packed = (const float*)d_in[0];
    const float* freqs  = (const float*)d_in[1];
    const float* gamp   = (const float*)d_in[2];
    const float* oamp   = (const float*)d_in[3];
    const float* noise  = (const float*)d_in[4];
    float* out = (float*)d_out;

    k_tw<<<32, 512>>>();
    k_prep<<<128, 128>>>(packed, freqs);

    cudaFuncSetAttribute(k_fft, cudaFuncAttributeMaxDynamicSharedMemorySize, 131072);
    k_fft<<<128, 512, 131072>>>(packed, noise, gamp);

    dim3 gs(16, 16);
    k_synth<<<gs, 256>>>(oamp, out);
}

// round 8
// speedup vs baseline: 2.1409x; 2.1409x over previous
#include <cuda_runtime.h>
#include <math.h>

#define NBATCH 128
#define NSAMP  32768
#define MHALF  16384
#define NFRAME 128
#define NHARM  8
#define PK_STRIDE 416

// skewed shared-memory index: kills small-stride bank conflicts in radix-4 stages
#define SKEW(i) ((i) + ((i) >> 4))
#define SD_FLOAT2 17408   // SKEW(16383)=17406 -> 17408 float2 = 139264 B

// ---------------- scratch (device globals; no allocation allowed) ----------------
__device__ float  g_r[NBATCH * NHARM];
__device__ float  g_res[NBATCH * NHARM * NFRAME];
__device__ float  g_noise[NBATCH * NSAMP];
__device__ float2 g_tw[MHALF];   // e^{-2 pi i k / 32768}, k=0..16383

// ---------------- twiddle table ----------------
__global__ void k_tw() {
    int k = blockIdx.x * blockDim.x + threadIdx.x;
    if (k < MHALF) {
        double ang = -6.283185307179586476925286766559 * (double)k / 32768.0;
        g_tw[k] = make_float2((float)cos(ang), (float)sin(ang));
    }
}

// ---------------- prep: softmax-dot f0, radians, envelope scan ----------------
__global__ void k_prep(const float* __restrict__ packed, const float* __restrict__ freqs) {
    int b = blockIdx.x;
    int t = threadIdx.x;           // 128 threads
    const float* p = packed + b * PK_STRIDE;

    __shared__ float  red[128];
    __shared__ double redd[128];
    __shared__ float  s_f0;
    __shared__ float  s_ampf[128];

    float x = p[t];
    red[t] = x;
    __syncthreads();
    for (int s = 64; s > 0; s >>= 1) {
        if (t < s) red[t] = fmaxf(red[t], red[t + s]);
        __syncthreads();
    }
    float mx = red[0];
    __syncthreads();

    float e = expf(x - mx);
    redd[t] = (double)e;
    __syncthreads();
    for (int s = 64; s > 0; s >>= 1) {
        if (t < s) redd[t] += redd[t + s];
        __syncthreads();
    }
    double esum = redd[0];
    __syncthreads();

    redd[t] = (double)e * (double)freqs[t];
    __syncthreads();
    for (int s = 64; s > 0; s >>= 1) {
        if (t < s) redd[t] += redd[t + s];
        __syncthreads();
    }
    if (t == 0) s_f0 = (float)(redd[0] / esum);
    s_ampf[t] = p[256 + t] * 2.0f - 1.0f;
    __syncthreads();

    if (t < NHARM) {
        const float NYQ    = 11025.0f;
        const float PIF    = 3.14159265358979323846f;
        const float MINF0  = (float)(40.0 / 11025.0);
        const float F0SPAN = (float)(3000.0 / 11025.0 - 40.0 / 11025.0);
        float f0s = s_f0;
        float f0  = f0s * f0s;
        f0 = f0 * NYQ;
        f0 = MINF0 + f0 * F0SPAN;
        float osc = f0 * (float)(t + 1);
        float rad = osc / NYQ * PIF;
        if (rad >= PIF) rad = 0.0f;
        g_r[b * NHARM + t] = rad;

        float ha = p[384 + t];
        float hd = 0.5f + p[392 + t] * 0.5f;
        float cur = 0.0f;
        float* dst = g_res + (b * NHARM + t) * NFRAME;
        for (int f = 0; f < NFRAME; f++) {
            cur = fmaxf(cur + s_ampf[f] * ha, 0.0f);
            dst[f] = cur;
            cur *= hd;
        }
    }
}

// ---------------- FFT helpers ----------------
__device__ __forceinline__ int rev4(int i) {   // base-4 digit reversal of 14-bit index
    unsigned r = __brev((unsigned)i) >> 18;
    return (int)(((r & 0x1555u) << 1) | ((r >> 1) & 0x1555u));
}

__device__ __forceinline__ float2 cmul(float2 a, float2 b) {
    return make_float2(a.x * b.x - a.y * b.y, a.x * b.y + a.y * b.x);
}

__device__ __forceinline__ float interp_amp_gate(const float* s_amp, int n) {
    float c = ((float)n + 0.5f) * (1.0f / 256.0f) - 0.5f;
    c = fminf(fmaxf(c, 0.0f), 127.0f);
    int   i0 = (int)c;
    float w  = c - (float)i0;
    int   i1 = min(i0 + 1, 127);
    float a  = s_amp[i0] * (1.0f - w) + s_amp[i1] * w;
    return a >= 0.0f ? a : 0.2f * a;
}

__device__ __forceinline__ float nf_eval(const float* env, int j) {
    if (j >= MHALF) return 0.0f;
    float c = ((float)j + 0.5f) * (16.0f / 16384.0f) - 0.5f;
    c = fminf(fmaxf(c, 0.0f), 15.0f);
    int   i0 = (int)c;
    float w  = c - (float)i0;
    int   i1 = min(i0 + 1, 15);
    return env[i0] * (1.0f - w) + env[i1] * w;
}

// ---------------- FFT filter kernel: radix-4 DIF fwd + DIT inv (no reorder passes) ----------------
__global__ void __launch_bounds__(512, 1)
k_fft(const float* __restrict__ packed, const float* __restrict__ noise,
      const float* __restrict__ gamp) {
    extern __shared__ float2 sd[];
    __shared__ float s_amp[128];
    __shared__ float s_env[16];

    int b = blockIdx.x;
    int t = threadIdx.x;
    const float* p = packed + b * PK_STRIDE;
    if (t < 128)       s_amp[t]       = p[256 + t] * 2.0f - 1.0f;
    else if (t < 144)  s_env[t - 128] = p[400 + (t - 128)];

    float ga = gamp[0];
    const float2* nz = reinterpret_cast<const float2*>(noise + (size_t)b * NSAMP);

    // coalesced natural-order load, z[n] = ga*(x[2n] + i x[2n+1])
    for (int i = t; i < MHALF; i += 512) {
        float2 v = nz[i];
        v.x *= ga; v.y *= ga;
        sd[SKEW(i)] = v;
    }
    __syncthreads();

    // ---- forward radix-4 DIF (e^-): natural in -> digit-reversed out ----
    // stage s: span 4q = 2^(14-2s); twiddle e^{-2pi i pos/4q} = g_tw[pos << (2s+1)]
#pragma unroll
    for (int s = 0; s < 7; s++) {
        int qb = 12 - 2 * s;
        int q  = 1 << qb;
        for (int j = t; j < 4096; j += 512) {
            int pos = j & (q - 1);
            int i0  = ((j >> qb) << (qb + 2)) + pos;
            float2 a  = sd[SKEW(i0)];
            float2 bb = sd[SKEW(i0 + q)];
            float2 c  = sd[SKEW(i0 + 2 * q)];
            float2 d  = sd[SKEW(i0 + 3 * q)];
            float2 t0 = make_float2(a.x + c.x,  a.y + c.y);
            float2 t1 = make_float2(a.x - c.x,  a.y - c.y);
            float2 t2 = make_float2(bb.x + d.x, bb.y + d.y);
            float2 t3 = make_float2(bb.x - d.x, bb.y - d.y);
            float2 y0 = make_float2(t0.x + t2.x, t0.y + t2.y);
            float2 y2 = make_float2(t0.x - t2.x, t0.y - t2.y);
            float2 y1 = make_float2(t1.x + t3.y, t1.y - t3.x);   // t1 - i*t3
            float2 y3 = make_float2(t1.x - t3.y, t1.y + t3.x);   // t1 + i*t3
            float2 w1 = g_tw[pos << (2 * s + 1)];                // FIXED shift
            float2 w2 = make_float2(w1.x * w1.x - w1.y * w1.y, 2.0f * w1.x * w1.y);
            float2 w3 = cmul(w1, w2);
            sd[SKEW(i0)]         = y0;
            sd[SKEW(i0 + q)]     = cmul(y1, w1);
            sd[SKEW(i0 + 2 * q)] = cmul(y2, w2);
            sd[SKEW(i0 + 3 * q)] = cmul(y3, w3);
        }
        __syncthreads();
    }

    // ---- middle: unpack real spectrum, filter by nf, repack (slots are digit-reversed) ----
    const float sc = 1.0f / 16384.0f;   // fold IFFT 1/M into filter
    for (int k = t; k <= 8192; k += 512) {
        int kk = (MHALF - k) & (MHALF - 1);
        int sj  = SKEW(rev4(k));
        int sjj = SKEW(rev4(kk));
        float2 Zk = sd[sj], Zm = sd[sjj];
        float2 Xe = make_float2(0.5f * (Zk.x + Zm.x), 0.5f * (Zk.y - Zm.y));
        float2 Xo = make_float2(0.5f * (Zk.y + Zm.y), 0.5f * (Zm.x - Zk.x));
        float a  = nf_eval(s_env, k);
        float bb = nf_eval(s_env, MHALF - k);
        float s = 0.5f * sc * (a + bb), d = 0.5f * sc * (a - bb);
        float2 w  = g_tw[k];
        float2 u  = make_float2(w.x * Xo.x - w.y * Xo.y, w.x * Xo.y + w.y * Xo.x);  // w*Xo
        float2 cw = make_float2(w.x * Xe.x + w.y * Xe.y, w.x * Xe.y - w.y * Xe.x);  // conj(w)*Xe
        float2 Ye = make_float2(s * Xe.x + d * u.x,  s * Xe.y + d * u.y);
        float2 Yo = make_float2(d * cw.x + s * Xo.x, d * cw.y + s * Xo.y);
        sd[sj]  = make_float2(Ye.x - Yo.y, Ye.y + Yo.x);
        sd[sjj] = make_float2(Ye.x + Yo.y, Yo.x - Ye.y);
    }
    __syncthreads();

    // ---- inverse radix-4 DIT (e^+): digit-reversed in -> natural out ----
    // stage s: span 4q = 2^(2s+2); twiddle e^{+2pi i pos/4q} = conj(g_tw[pos << (13-2s)])
#pragma unroll
    for (int s = 0; s < 7; s++) {
        int qb  = 2 * s;
        int q   = 1 << qb;
        int tsh = 13 - 2 * s;                               // FIXED shift
        for (int j = t; j < 4096; j += 512) {
            int pos = j & (q - 1);
            int i0  = ((j >> qb) << (qb + 2)) + pos;
            float2 w1 = g_tw[pos << tsh];
            w1.y = -w1.y;                                   // conj -> e^{+}
            float2 w2 = make_float2(w1.x * w1.x - w1.y * w1.y, 2.0f * w1.x * w1.y);
            float2 w3 = cmul(w1, w2);
            float2 a  = sd[SKEW(i0)];
            float2 bb = cmul(sd[SKEW(i0 + q)],     w1);
            float2 c  = cmul(sd[SKEW(i0 + 2 * q)], w2);
            float2 d  = cmul(sd[SKEW(i0 + 3 * q)], w3);
            float2 t0 = make_float2(a.x + c.x,  a.y + c.y);
            float2 t1 = make_float2(a.x - c.x,  a.y - c.y);
            float2 t2 = make_float2(bb.x + d.x, bb.y + d.y);
            float2 t3 = make_float2(bb.x - d.x, bb.y - d.y);
            sd[SKEW(i0)]         = make_float2(t0.x + t2.x, t0.y + t2.y);
            sd[SKEW(i0 + q)]     = make_float2(t1.x - t3.y, t1.y + t3.x);   // t1 + i*t3
            sd[SKEW(i0 + 2 * q)] = make_float2(t0.x - t2.x, t0.y - t2.y);
            sd[SKEW(i0 + 3 * q)] = make_float2(t1.x + t3.y, t1.y - t3.x);   // t1 - i*t3
        }
        __syncthreads();
    }

    // ---- natural-order writeout: conflict-free smem read, coalesced global store ----
    float2* gn = reinterpret_cast<float2*>(g_noise + (size_t)b * NSAMP);
    for (int n = t; n < MHALF; n += 512) {
        float2 wv = sd[SKEW(n)];
        float a0 = interp_amp_gate(s_amp, 2 * n);
        float a1 = interp_amp_gate(s_amp, 2 * n + 1);
        gn[n] = make_float2(wv.x * a0, wv.y * a1);
    }
}

// ---------------- synth + reduce ----------------
__device__ __forceinline__ float phase_red(float nf, float r) {
    float pv  = r * nf;
    float err = fmaf(r, nf, -pv);
    float k   = rintf(pv * 0.15915494309189535f);
    float ph  = fmaf(k, -6.2831854820251465f, pv);
    ph = fmaf(k, 1.7484556e-7f, ph);
    return ph + err;
}

__global__ void __launch_bounds__(256)
k_synth(const float* __restrict__ oamp, float* __restrict__ out) {
    int g = blockIdx.y;      // 16 groups of 8 batches
    int chunk = blockIdx.x;  // 16 chunks of 2048 samples
    int t = threadIdx.x;

    __shared__ float  s_res[64 * 128];
    __shared__ float  s_r[64];
    __shared__ float2 s_rot[64];   // e^{i*256*r} per (batch,harm)

    for (int i = t; i < 64 * 128; i += 256)
        s_res[i] = g_res[g * 64 * NFRAME + i];
    if (t < 64) {
        float r = g_r[g * 64 + t];
        s_r[t] = r;
        float pr = phase_red(256.0f, r);    // 256*r exact (power of 2)
        float sn, cs;
        sincosf(pr, &sn, &cs);
        s_rot[t] = make_float2(cs, sn);
    }
    __syncthreads();

    float oa = oamp[0];
    int nbase = chunk * 2048 + t;

    float accN[8], accO[8];
#pragma unroll
    for (int i = 0; i < 8; i++) { accN[i] = 0.0f; accO[i] = 0.0f; }

    // noise part
#pragma unroll
    for (int j = 0; j < 8; j++) {
        const float* nb = g_noise + (size_t)(g * 8 + j) * NSAMP;
#pragma unroll
        for (int i = 0; i < 8; i++) accN[i] += nb[nbase + i * 256];
    }

    // precompute interpolation coords (same for all bh)
    int i0a[8], i1a[8];
    float wa[8];
#pragma unroll
    for (int i = 0; i < 8; i++) {
        int n = nbase + i * 256;
        float c = ((float)n + 0.5f) * (1.0f / 256.0f) - 0.5f;
        c = fminf(fmaxf(c, 0.0f), 127.0f);
        int i0 = (int)c;
        wa[i]  = c - (float)i0;
        i0a[i] = i0;
        i1a[i] = min(i0 + 1, 127);
    }

    float nf1 = (float)(nbase + 1);
#pragma unroll 1
    for (int bh = 0; bh < 64; bh++) {
        float r = s_r[bh];
        if (r == 0.0f) continue;           // clamped harmonic: sin(0)=0
        float2 rot = s_rot[bh];
        float ph = phase_red(nf1, r);
        float sn, cs;
        sincosf(ph, &sn, &cs);
        const float* rr = s_res + bh * 128;
#pragma unroll
        for (int i = 0; i < 8; i++) {
            float r0 = rr[i0a[i]];
            float rv = fmaf(wa[i], rr[i1a[i]] - r0, r0);
            accO[i] = fmaf(rv, sn, accO[i]);
            float ns = fmaf(sn, rot.x, cs * rot.y);
            cs = fmaf(cs, rot.x, -sn * rot.y);
            sn = ns;
        }
    }

#pragma unroll
    for (int i = 0; i < 8; i++)
        out[(size_t)g * NSAMP + nbase + i * 256] = fmaf(accO[i], oa, accN[i]);
}

// ---------------- launch ----------------
extern "C" void kernel_launch(void* const* d_in, const int* in_sizes, int n_in,
                              void* d_out, int out_size) {
    const float* packed = (const float*)d_in[0];
    const float* freqs  = (const float*)d_in[1];
    const float* gamp   = (const float*)d_in[2];
    const float* oamp   = (const float*)d_in[3];
    const float* noise  = (const float*)d_in[4];
    float* out = (float*)d_out;

    k_tw<<<32, 512>>>();
    k_prep<<<128, 128>>>(packed, freqs);

    cudaFuncSetAttribute(k_fft, cudaFuncAttributeMaxDynamicSharedMemorySize, SD_FLOAT2 * 8);
    k_fft<<<128, 512, SD_FLOAT2 * 8>>>(packed, noise, gamp);

    dim3 gs(16, 16);
    k_synth<<<gs, 256>>>(oamp, out);
}

// round 12
// speedup vs baseline: 2.6667x; 1.2456x over previous
#include <cuda_runtime.h>
#include <math.h>

#define NBATCH 128
#define NSAMP  32768
#define MHALF  16384
#define NFRAME 128
#define NHARM  8
#define PK_STRIDE 416

// ---- XOR bank swizzle: phys(i) = i ^ F(i); F folds bits 5,6,8,10..13 into low 5 bits.
// bit5->9, bit6->22, bit8->1, bit9->0, bit10..13->2,4,8,16. Conflict-free for all
// stage strides, the middle rev4 scatter (both k and 16384-k sides), and stride-1 IO.
#define FVAL(i) ((int)((((0x1F160900u >> (((unsigned)(i) >> 2) & 0x18u)) & 31u)) ^ (((i) >> 8) & 1) ^ (((i) >> 9) & 30)))
__device__ __forceinline__ int physx(int i) { return i ^ FVAL(i); }

// ---------------- scratch (device globals; no allocation allowed) ----------------
__device__ float  g_r[NBATCH * NHARM];
__device__ float  g_res[NBATCH * NHARM * NFRAME];
__device__ float  g_noise[NBATCH * NSAMP];
__device__ float2 g_tw[MHALF];      // e^{-2 pi i k / 32768}  (middle pass, coalesced)
__device__ float2 g_tws[5461];      // stage-packed twiddles: stage s (fwd): e^{-2 pi i p / 2^(14-2s)}

// stage offsets into g_tws: sizes 4096,1024,256,64,16,4,1
#define OFS0 0
#define OFS1 4096
#define OFS2 5120
#define OFS3 5376
#define OFS4 5440
#define OFS5 5456
#define OFS6 5460

// ---------------- twiddle tables ----------------
__global__ void k_tw() {
    int k = blockIdx.x * blockDim.x + threadIdx.x;
    const double TWO_PI = 6.283185307179586476925286766559;
    if (k < MHALF) {
        double ang = -TWO_PI * (double)k / 32768.0;
        g_tw[k] = make_float2((float)cos(ang), (float)sin(ang));
    }
    if (k < 5461) {
        int off = 0, s = 0, o = 0;
#pragma unroll
        for (int ss = 0; ss < 7; ss++) {
            int sz = 4096 >> (2 * ss);
            if (k >= off && k < off + sz) { s = ss; o = k - off; }
            off += sz;
        }
        double denom = (double)(1 << (14 - 2 * s));
        double ang = -TWO_PI * (double)o / denom;
        g_tws[k] = make_float2((float)cos(ang), (float)sin(ang));
    }
}

// ---------------- prep: softmax-dot f0, radians, envelope scan ----------------
__global__ void k_prep(const float* __restrict__ packed, const float* __restrict__ freqs) {
    int b = blockIdx.x;
    int t = threadIdx.x;           // 128 threads
    const float* p = packed + b * PK_STRIDE;

    __shared__ float  red[128];
    __shared__ double redd[128];
    __shared__ float  s_f0;
    __shared__ float  s_ampf[128];

    float x = p[t];
    red[t] = x;
    __syncthreads();
    for (int s = 64; s > 0; s >>= 1) {
        if (t < s) red[t] = fmaxf(red[t], red[t + s]);
        __syncthreads();
    }
    float mx = red[0];
    __syncthreads();

    float e = expf(x - mx);
    redd[t] = (double)e;
    __syncthreads();
    for (int s = 64; s > 0; s >>= 1) {
        if (t < s) redd[t] += redd[t + s];
        __syncthreads();
    }
    double esum = redd[0];
    __syncthreads();

    redd[t] = (double)e * (double)freqs[t];
    __syncthreads();
    for (int s = 64; s > 0; s >>= 1) {
        if (t < s) redd[t] += redd[t + s];
        __syncthreads();
    }
    if (t == 0) s_f0 = (float)(redd[0] / esum);
    s_ampf[t] = p[256 + t] * 2.0f - 1.0f;
    __syncthreads();

    if (t < NHARM) {
        const float NYQ    = 11025.0f;
        const float PIF    = 3.14159265358979323846f;
        const float MINF0  = (float)(40.0 / 11025.0);
        const float F0SPAN = (float)(3000.0 / 11025.0 - 40.0 / 11025.0);
        float f0s = s_f0;
        float f0  = f0s * f0s;
        f0 = f0 * NYQ;
        f0 = MINF0 + f0 * F0SPAN;
        float osc = f0 * (float)(t + 1);
        float rad = osc / NYQ * PIF;
        if (rad >= PIF) rad = 0.0f;
        g_r[b * NHARM + t] = rad;

        float ha = p[384 + t];
        float hd = 0.5f + p[392 + t] * 0.5f;
        float cur = 0.0f;
        float* dst = g_res + (b * NHARM + t) * NFRAME;
        for (int f = 0; f < NFRAME; f++) {
            cur = fmaxf(cur + s_ampf[f] * ha, 0.0f);
            dst[f] = cur;
            cur *= hd;
        }
    }
}

// ---------------- FFT helpers ----------------
__device__ __forceinline__ int rev4(int i) {   // base-4 digit reversal of 14-bit index
    unsigned r = __brev((unsigned)i) >> 18;
    return (int)(((r & 0x1555u) << 1) | ((r >> 1) & 0x1555u));
}

__device__ __forceinline__ float2 cmul(float2 a, float2 b) {
    return make_float2(a.x * b.x - a.y * b.y, a.x * b.y + a.y * b.x);
}

__device__ __forceinline__ float interp_amp_gate(const float* s_amp, int n) {
    float c = ((float)n + 0.5f) * (1.0f / 256.0f) - 0.5f;
    c = fminf(fmaxf(c, 0.0f), 127.0f);
    int   i0 = (int)c;
    float w  = c - (float)i0;
    int   i1 = min(i0 + 1, 127);
    float a  = s_amp[i0] * (1.0f - w) + s_amp[i1] * w;
    return a >= 0.0f ? a : 0.2f * a;
}

__device__ __forceinline__ float nf_eval(const float* env, int j) {
    if (j >= MHALF) return 0.0f;
    float c = ((float)j + 0.5f) * (16.0f / 16384.0f) - 0.5f;
    c = fminf(fmaxf(c, 0.0f), 15.0f);
    int   i0 = (int)c;
    float w  = c - (float)i0;
    int   i1 = min(i0 + 1, 15);
    return env[i0] * (1.0f - w) + env[i1] * w;
}

// ---------------- FFT filter kernel: radix-4 DIF fwd + DIT inv, XOR-swizzled smem ----------------
__global__ void __launch_bounds__(512, 1)
k_fft(const float* __restrict__ packed, const float* __restrict__ noise,
      const float* __restrict__ gamp) {
    extern __shared__ float2 sd[];    // 16384 float2 = 131072 B, XOR-permuted
    __shared__ float s_amp[128];
    __shared__ float s_env[16];

    int b = blockIdx.x;
    int t = threadIdx.x;
    const float* p = packed + b * PK_STRIDE;
    if (t < 128)       s_amp[t]       = p[256 + t] * 2.0f - 1.0f;
    else if (t < 144)  s_env[t - 128] = p[400 + (t - 128)];

    float ga = gamp[0];
    const float2* nz = reinterpret_cast<const float2*>(noise + (size_t)b * NSAMP);

    // coalesced natural-order load, z[n] = ga*(x[2n] + i x[2n+1])
    for (int i = t; i < MHALF; i += 512) {
        float2 v = nz[i];
        v.x *= ga; v.y *= ga;
        sd[physx(i)] = v;
    }
    __syncthreads();

    const int OFS[7] = {OFS0, OFS1, OFS2, OFS3, OFS4, OFS5, OFS6};

    // ---- forward radix-4 DIF (e^-): natural in -> digit-reversed out ----
#pragma unroll
    for (int s = 0; s < 7; s++) {
        const int qb = 12 - 2 * s;
        const int q  = 1 << qb;
        const int D1 = FVAL(q), D2 = FVAL(2 * q), D3 = FVAL(3 * q);
        const float2* twp = g_tws + OFS[s];
        for (int j = t; j < 4096; j += 512) {
            int pos = j & (q - 1);
            int i0  = ((j >> qb) << (qb + 2)) + pos;
            int f0  = FVAL(i0);
            int p0  = i0 ^ f0;
            int p1  = (i0 + q)     ^ (f0 ^ D1);
            int p2  = (i0 + 2 * q) ^ (f0 ^ D2);
            int p3  = (i0 + 3 * q) ^ (f0 ^ D3);
            float2 a  = sd[p0];
            float2 bb = sd[p1];
            float2 c  = sd[p2];
            float2 d  = sd[p3];
            float2 t0 = make_float2(a.x + c.x,  a.y + c.y);
            float2 t1 = make_float2(a.x - c.x,  a.y - c.y);
            float2 t2 = make_float2(bb.x + d.x, bb.y + d.y);
            float2 t3 = make_float2(bb.x - d.x, bb.y - d.y);
            float2 y0 = make_float2(t0.x + t2.x, t0.y + t2.y);
            float2 y2 = make_float2(t0.x - t2.x, t0.y - t2.y);
            float2 y1 = make_float2(t1.x + t3.y, t1.y - t3.x);   // t1 - i*t3
            float2 y3 = make_float2(t1.x - t3.y, t1.y + t3.x);   // t1 + i*t3
            float2 w1 = twp[pos];
            float2 w2 = make_float2(w1.x * w1.x - w1.y * w1.y, 2.0f * w1.x * w1.y);
            float2 w3 = cmul(w1, w2);
            sd[p0] = y0;
            sd[p1] = cmul(y1, w1);
            sd[p2] = cmul(y2, w2);
            sd[p3] = cmul(y3, w3);
        }
        __syncthreads();
    }

    // ---- middle: unpack real spectrum, filter by nf, repack (digit-reversed slots) ----
    const float sc = 1.0f / 16384.0f;   // fold IFFT 1/M into filter
    for (int k = t; k <= 8192; k += 512) {
        int kk = (MHALF - k) & (MHALF - 1);
        int sj  = physx(rev4(k));
        int sjj = physx(rev4(kk));
        float2 Zk = sd[sj], Zm = sd[sjj];
        float2 Xe = make_float2(0.5f * (Zk.x + Zm.x), 0.5f * (Zk.y - Zm.y));
        float2 Xo = make_float2(0.5f * (Zk.y + Zm.y), 0.5f * (Zm.x - Zk.x));
        float a  = nf_eval(s_env, k);
        float bb = nf_eval(s_env, MHALF - k);
        float s = 0.5f * sc * (a + bb), d = 0.5f * sc * (a - bb);
        float2 w  = g_tw[k];
        float2 u  = make_float2(w.x * Xo.x - w.y * Xo.y, w.x * Xo.y + w.y * Xo.x);  // w*Xo
        float2 cw = make_float2(w.x * Xe.x + w.y * Xe.y, w.x * Xe.y - w.y * Xe.x);  // conj(w)*Xe
        float2 Ye = make_float2(s * Xe.x + d * u.x,  s * Xe.y + d * u.y);
        float2 Yo = make_float2(d * cw.x + s * Xo.x, d * cw.y + s * Xo.y);
        sd[sj]  = make_float2(Ye.x - Yo.y, Ye.y + Yo.x);
        sd[sjj] = make_float2(Ye.x + Yo.y, Yo.x - Ye.y);
    }
    __syncthreads();

    // ---- inverse radix-4 DIT (e^+): digit-reversed in -> natural out ----
#pragma unroll
    for (int s = 0; s < 7; s++) {
        const int qb = 2 * s;
        const int q  = 1 << qb;
        const int D1 = FVAL(q), D2 = FVAL(2 * q), D3 = FVAL(3 * q);
        const float2* twp = g_tws + OFS[6 - s];   // same table, conj applied below
        for (int j = t; j < 4096; j += 512) {
            int pos = j & (q - 1);
            int i0  = ((j >> qb) << (qb + 2)) + pos;
            int f0  = FVAL(i0);
            int p0  = i0 ^ f0;
            int p1  = (i0 + q)     ^ (f0 ^ D1);
            int p2  = (i0 + 2 * q) ^ (f0 ^ D2);
            int p3  = (i0 + 3 * q) ^ (f0 ^ D3);
            float2 w1 = twp[pos];
            w1.y = -w1.y;                                   // conj -> e^{+}
            float2 w2 = make_float2(w1.x * w1.x - w1.y * w1.y, 2.0f * w1.x * w1.y);
            float2 w3 = cmul(w1, w2);
            float2 a  = sd[p0];
            float2 bb = cmul(sd[p1], w1);
            float2 c  = cmul(sd[p2], w2);
            float2 d  = cmul(sd[p3], w3);
            float2 t0 = make_float2(a.x + c.x,  a.y + c.y);
            float2 t1 = make_float2(a.x - c.x,  a.y - c.y);
            float2 t2 = make_float2(bb.x + d.x, bb.y + d.y);
            float2 t3 = make_float2(bb.x - d.x, bb.y - d.y);
            sd[p0] = make_float2(t0.x + t2.x, t0.y + t2.y);
            sd[p1] = make_float2(t1.x - t3.y, t1.y + t3.x);   // t1 + i*t3
            sd[p2] = make_float2(t0.x - t2.x, t0.y - t2.y);
            sd[p3] = make_float2(t1.x + t3.y, t1.y - t3.x);   // t1 - i*t3
        }
        __syncthreads();
    }

    // ---- natural-order writeout ----
    float2* gn = reinterpret_cast<float2*>(g_noise + (size_t)b * NSAMP);
    for (int n = t; n < MHALF; n += 512) {
        float2 wv = sd[physx(n)];
        float a0 = interp_amp_gate(s_amp, 2 * n);
        float a1 = interp_amp_gate(s_amp, 2 * n + 1);
        gn[n] = make_float2(wv.x * a0, wv.y * a1);
    }
}

// ---------------- synth + reduce ----------------
__device__ __forceinline__ float phase_red(float nf, float r) {
    float pv  = r * nf;
    float err = fmaf(r, nf, -pv);
    float k   = rintf(pv * 0.15915494309189535f);
    float ph  = fmaf(k, -6.2831854820251465f, pv);
    ph = fmaf(k, 1.7484556e-7f, ph);
    return ph + err;
}

__global__ void __launch_bounds__(256)
k_synth(const float* __restrict__ oamp, float* __restrict__ out) {
    int g = blockIdx.y;      // 16 groups of 8 batches
    int chunk = blockIdx.x;  // 16 chunks of 2048 samples
    int t = threadIdx.x;

    __shared__ float s_res[64 * 128];
    __shared__ float s_r[64];
    __shared__ float s_c2[64];       // 2*cos(r)

    for (int i = t; i < 64 * 128; i += 256)
        s_res[i] = g_res[g * 64 * NFRAME + i];
    if (t < 64) {
        float r = g_r[g * 64 + t];
        s_r[t]  = r;
        s_c2[t] = 2.0f * cosf(r);
    }
    __syncthreads();

    int n0 = chunk * 2048 + t * 8;   // 8 consecutive samples per thread

    // noise part: vectorized loads, sum over the 8 batches of this group
    float acc[8];
#pragma unroll
    for (int i = 0; i < 8; i++) acc[i] = 0.0f;
#pragma unroll
    for (int j = 0; j < 8; j++) {
        const float4* nb4 = reinterpret_cast<const float4*>(g_noise + (size_t)(g * 8 + j) * NSAMP + n0);
        float4 v0 = nb4[0], v1 = nb4[1];
        acc[0] += v0.x; acc[1] += v0.y; acc[2] += v0.z; acc[3] += v0.w;
        acc[4] += v1.x; acc[5] += v1.y; acc[6] += v1.z; acc[7] += v1.w;
    }

    // interp weights (shared across all bh): two-segment branch-free form
    float w8[8], u8[8];
    float c0 = fminf(fmaxf(((float)n0 + 0.5f) * (1.0f / 256.0f) - 0.5f, 0.0f), 127.0f);
    int i0b = (int)c0;
#pragma unroll
    for (int i = 0; i < 8; i++) {
        float ci = fminf(fmaxf(((float)(n0 + i) + 0.5f) * (1.0f / 256.0f) - 0.5f, 0.0f), 127.0f);
        float w = ci - (float)i0b;
        w8[i] = w;
        u8[i] = fmaxf(w - 1.0f, 0.0f);
    }
    int iB = min(i0b + 1, 127), iC = min(i0b + 2, 127);

    float nf1 = (float)(n0 + 1);
    float nf0 = (float)n0;
    float accO[8];
#pragma unroll
    for (int i = 0; i < 8; i++) accO[i] = 0.0f;

#pragma unroll 1
    for (int bh = 0; bh < 64; bh++) {
        float r = s_r[bh];
        if (r == 0.0f) continue;           // clamped harmonic contributes sin(0)=0
        const float* rr = s_res + bh * 128;
        float rA = rr[i0b], rB = rr[iB], rC = rr[iC];
        float d0 = rB - rA;
        float dd = (rC - rB) - d0;
        float c2 = s_c2[bh];
        float s1 = __sinf(phase_red(nf1, r));   // sin((n0+1) r)
        float s0 = __sinf(phase_red(nf0, r));   // sin(n0 r)
#pragma unroll
        for (int i = 0; i < 8; i++) {
            float rv = fmaf(u8[i], dd, fmaf(w8[i], d0, rA));
            accO[i] = fmaf(rv, s1, accO[i]);
            float s2 = fmaf(c2, s1, -s0);       // Chebyshev: sin((n+1)r)
            s0 = s1; s1 = s2;
        }
    }

    float oa = oamp[0];
    float4 o0 = make_float4(fmaf(accO[0], oa, acc[0]), fmaf(accO[1], oa, acc[1]),
                            fmaf(accO[2], oa, acc[2]), fmaf(accO[3], oa, acc[3]));
    float4 o1 = make_float4(fmaf(accO[4], oa, acc[4]), fmaf(accO[5], oa, acc[5]),
                            fmaf(accO[6], oa, acc[6]), fmaf(accO[7], oa, acc[7]));
    float4* op = reinterpret_cast<float4*>(out + (size_t)g * NSAMP + n0);
    op[0] = o0;
    op[1] = o1;
}

// ---------------- launch ----------------
extern "C" void kernel_launch(void* const* d_in, const int* in_sizes, int n_in,
                              void* d_out, int out_size) {
    const float* packed = (const float*)d_in[0];
    const float* freqs  = (const float*)d_in[1];
    const float* gamp   = (const float*)d_in[2];
    const float* oamp   = (const float*)d_in[3];
    const float* noise  = (const float*)d_in[4];
    float* out = (float*)d_out;

    k_tw<<<32, 512>>>();
    k_prep<<<128, 128>>>(packed, freqs);

    cudaFuncSetAttribute(k_fft, cudaFuncAttributeMaxDynamicSharedMemorySize, 131072);
    k_fft<<<128, 512, 131072>>>(packed, noise, gamp);

    dim3 gs(16, 16);
    k_synth<<<gs, 256>>>(oamp, out);
}